// round 11
// baseline (speedup 1.0000x reference)
#include <cuda_runtime.h>

#define DPRED    84
#define NCLS     80
#define MAXB     8
#define MAXA     76725
#define NBINS    4096
#define KMAX     512
#define NW       (KMAX / 32)
#define KTARGET  128
#define MAXDET   100
#define CONF_T   0.05f
#define IOU_T    0.5f
#define NMS_NT   512

typedef unsigned long long u64;
typedef unsigned int       u32;

// dynamic smem layout (bytes), alignment-descending
#define SM_P1    0
#define SM_SK    (SM_P1  + KMAX * 16)
#define SM_P2    (SM_SK  + KMAX * 8)
#define SM_MAT   (SM_P2  + KMAX * 8)
#define SM_CAND  (SM_MAT + KMAX * NW * 4)
#define SM_FLAG  (SM_CAND + KMAX * 4)
#define SM_DEAD  (SM_FLAG + NW * 4)
#define SM_ALIVE (SM_DEAD + NW * 4)
#define NMS_SMEM (SM_ALIVE + KMAX * 2)

// ---------------- device scratch (no allocation allowed) ----------------
__device__ float4 g_boxes8[MAXB * MAXA * 2];  // cx,cy,w,h | cls,conf,0,0
__device__ float  g_scores[MAXB * MAXA];      // conf if >= CONF_T else 0
__device__ int    g_hist[MAXB * NBINS];       // zero-init; re-zeroed by thresh
__device__ float  g_thresh[MAXB];

// ---------------- decode: 4 threads per anchor ----------------
__global__ void __launch_bounds__(256)
decode_kernel(const float* __restrict__ pred,
              const float* __restrict__ anchors,
              int B, int A) {
    int gt = blockIdx.x * blockDim.x + threadIdx.x;
    int i  = gt >> 2;            // anchor
    int q  = gt & 3;             // lane within quad
    if (i >= B * A) return;

    const float4* row = reinterpret_cast<const float4*>(pred + (size_t)i * DPRED);

    float4 v0 = make_float4(0.f, 0.f, 0.f, 0.f);
    if (q == 0) v0 = __ldg(row);

    // each quad-lane scans float4s j = q, q+4, ... (lane 0 skips j=0 logits-wise)
    float best = -3.4e38f;
    int   cls  = 1 << 30;
    for (int j = (q == 0 ? 4 : q); j < DPRED / 4; j += 4) {
        float4 c = __ldg(row + j);
        int base = j * 4 - 4;
        if (c.x > best) { best = c.x; cls = base + 0; }
        if (c.y > best) { best = c.y; cls = base + 1; }
        if (c.z > best) { best = c.z; cls = base + 2; }
        if (c.w > best) { best = c.w; cls = base + 3; }
    }

    // intra-quad reduction, first-occurrence tie-break
    unsigned qm = 0xFu << ((threadIdx.x & 31) & ~3);
#pragma unroll
    for (int off = 1; off <= 2; off <<= 1) {
        float ob = __shfl_xor_sync(qm, best, off);
        int   oi = __shfl_xor_sync(qm, cls, off);
        if (ob > best || (ob == best && oi < cls)) { best = ob; cls = oi; }
    }

    if (q == 0) {
        int b = i / A;
        int a = i - b * A;
        float4 an = __ldg(reinterpret_cast<const float4*>(anchors) + a);
        float cx = v0.x * 0.1f * an.z + an.x;
        float cy = v0.y * 0.1f * an.w + an.y;
        float w  = expf(v0.z * 0.2f) * an.z;
        float h  = expf(v0.w * 0.2f) * an.w;
        float conf = 1.0f / (1.0f + expf(-best));

        g_boxes8[(size_t)i * 2 + 0] = make_float4(cx, cy, w, h);
        g_boxes8[(size_t)i * 2 + 1] = make_float4((float)cls, conf, 0.f, 0.f);

        float s = (conf >= CONF_T) ? conf : 0.0f;
        g_scores[i] = s;
        if (s > 0.0f) {
            int bin = (int)(s * (float)NBINS);
            if (bin > NBINS - 1) bin = NBINS - 1;
            if (bin < 1) bin = 1;
            atomicAdd(&g_hist[b * NBINS + bin], 1);
        }
    }
}

// ------- threshold from histogram (and re-zero hist for next call) -------
__global__ void __launch_bounds__(512)
thresh_kernel() {
    int b   = blockIdx.x;
    int tid = threadIdx.x;
    __shared__ int sh[NBINS];
    __shared__ int csum[128];

    for (int i = tid; i < NBINS; i += 512)
        sh[i] = g_hist[b * NBINS + i];
    __syncthreads();
    for (int i = tid; i < NBINS; i += 512)
        g_hist[b * NBINS + i] = 0;

    if (tid < 128) {
        int s = 0, base = tid * 32;
#pragma unroll
        for (int j = 0; j < 32; j++) s += sh[base + j];
        csum[tid] = s;
    }
    __syncthreads();

    if (tid == 0) {
        int cum = 0, binSel = NBINS, c = 128;
        while (c > 1 && cum < KTARGET && cum + csum[c - 1] <= KMAX) {
            c--; cum += csum[c]; binSel = c * 32;
        }
        if (cum < KTARGET && c >= 1) {
            for (int bin = c * 32 - 1; bin >= (c - 1) * 32 && bin >= 1; --bin) {
                int h = sh[bin];
                if (cum + h > KMAX) break;
                cum += h; binSel = bin;
                if (cum >= KTARGET) break;
            }
        }
        g_thresh[b] = (float)binSel / (float)NBINS;
    }
}

// ---- NMS: in-kernel compact + sort + suppression matrix + resolve -------
__global__ void __launch_bounds__(NMS_NT, 1)
nms_kernel(float* __restrict__ out, int A) {
    extern __shared__ char dynsm[];
    float4* p1    = (float4*)(dynsm + SM_P1);     // x1,y1,x2,y2 (sorted)
    u64*    sk    = (u64*)   (dynsm + SM_SK);
    float2* p2    = (float2*)(dynsm + SM_P2);     // area, cls   (sorted)
    u32*    mat   = (u32*)   (dynsm + SM_MAT);
    int*    scand = (int*)   (dynsm + SM_CAND);
    u32*    flagm = (u32*)   (dynsm + SM_FLAG);
    u32*    sdead = (u32*)   (dynsm + SM_DEAD);
    unsigned short* aliveL = (unsigned short*)(dynsm + SM_ALIVE);

    __shared__ int sFallback, sCtr;
    __shared__ u64 sBest;
    __shared__ u64 redk[NMS_NT / 32];

    int b   = blockIdx.x;
    int tid = threadIdx.x;

    if (tid == 0) sCtr = 0;
    if (tid < NW) { flagm[tid] = 0; sdead[tid] = 0; }
    __syncthreads();

    // ---- in-kernel compact: scores > thresh -> candidate list ----
    float th = g_thresh[b];
    const float* sc = g_scores + (size_t)b * A;
    for (int i = tid; i < A; i += NMS_NT) {
        if (sc[i] > th) {
            int p = atomicAdd(&sCtr, 1);
            if (p < KMAX) scand[p] = i;
        }
    }
    __syncthreads();

    int cnt = sCtr;
    bool overflow = (cnt > KMAX);
    if (cnt > KMAX) cnt = KMAX;
    if (tid == 0) sFallback = overflow ? 1 : 0;

    // keys (conf hi, 0x7FFFFFFF - anchor lo); pad with 0
    for (int i = tid; i < KMAX; i += NMS_NT) {
        u64 k = 0;
        if (i < cnt) {
            int a = scand[i];
            float4 q1 = g_boxes8[((size_t)b * A + a) * 2 + 1];
            k = ((u64)__float_as_uint(q1.y) << 32) | (u32)(0x7FFFFFFF - a);
        }
        sk[i] = k;
    }
    __syncthreads();

    // ---- bitonic sort, descending ----
    for (int k2 = 2; k2 <= KMAX; k2 <<= 1) {
        for (int j2 = k2 >> 1; j2 > 0; j2 >>= 1) {
            int i = tid;
            int p = i ^ j2;
            if (i < KMAX && p > i) {
                u64 a = sk[i], c = sk[p];
                bool descBlk = ((i & k2) == 0);
                if (descBlk ? (a < c) : (a > c)) { sk[i] = c; sk[p] = a; }
            }
            __syncthreads();
        }
    }

    // ---- gather packed box data for sorted slots ----
    for (int s = tid; s < KMAX; s += NMS_NT) {
        u64 key = sk[s];
        if (s < cnt) {
            int a = 0x7FFFFFFF - (int)(key & 0xFFFFFFFFull);
            size_t base = ((size_t)b * A + a) * 2;
            float4 q0 = g_boxes8[base + 0];
            float4 q1 = g_boxes8[base + 1];
            float hw = 0.5f * q0.z, hh = 0.5f * q0.w;
            p1[s] = make_float4(q0.x - hw, q0.y - hh, q0.x + hw, q0.y + hh);
            p2[s] = make_float2(q0.z * q0.w, q1.x);
        } else {
            p1[s] = make_float4(0.f, 0.f, 0.f, 0.f);
            p2[s] = make_float2(0.f, -2.f);
        }
    }
    __syncthreads();

    // ---- suppression matrix: task = (row i, 32-wide j word), balanced ----
    for (int tsk = tid; tsk < KMAX * NW; tsk += NMS_NT) {
        int i  = tsk >> 4;           // NW = 16
        int jw = tsk & (NW - 1);
        if (i >= cnt) continue;      // row never read
        int jbase = jw << 5;
        if (jbase + 31 <= i || jbase >= cnt) { mat[tsk] = 0; continue; }

        float4 bi = p1[i];
        float2 ai = p2[i];
        u32 bits = 0;
#pragma unroll
        for (int jj = 0; jj < 32; jj++) {
            int j = jbase + jj;
            float4 bj = p1[j];
            float2 aj = p2[j];
            float iw = fminf(bj.z, bi.z) - fmaxf(bj.x, bi.x);
            float ih = fminf(bj.w, bi.w) - fmaxf(bj.y, bi.y);
            float inter = fmaxf(iw, 0.f) * fmaxf(ih, 0.f);
            float iou = inter / (aj.x + ai.x - inter + 1e-8f);
            bool sup = (j > i) && (j < cnt) && (aj.y == ai.y) && (iou > IOU_T);
            bits |= sup ? (1u << jj) : 0u;
        }
        mat[tsk] = bits;
        if (bits) atomicOr(&flagm[i >> 5], 1u << (i & 31));
    }
    __syncthreads();

    // ---- resolve: greedy over sorted order via bitmasks (serial, tiny) ----
    if (tid == 0 && !sFallback) {
        int aliveCnt = 0;
#pragma unroll
        for (int w = 0; w < NW; w++) {
            int lo = w * 32;
            int nvalid = cnt - lo;
            if (nvalid <= 0) break;
            u32 validm = (nvalid >= 32) ? 0xFFFFFFFFu : ((1u << nvalid) - 1u);
            u32 candm = validm & ~sdead[w];
            u32 fl = flagm[w];
            while (candm) {
                int bb = __ffs(candm) - 1;
                candm &= candm - 1;
                aliveL[aliveCnt++] = (unsigned short)(lo + bb);
                if (fl & (1u << bb)) {
                    int i = lo + bb;
#pragma unroll
                    for (int ww = 0; ww < NW; ww++)
                        sdead[ww] |= mat[i * NW + ww];
                    candm &= ~sdead[w];
                }
            }
        }
        if (aliveCnt < MAXDET) sFallback = 1;   // pool exhausted -> exact
    }
    __syncthreads();

    // ---- output: first MAXDET alive in sorted order ----
    if (!sFallback) {
        if (tid < MAXDET) {
            int s = aliveL[tid];
            u64 key = sk[s];
            int a = 0x7FFFFFFF - (int)(key & 0xFFFFFFFFull);
            size_t base = ((size_t)b * A + a) * 2;
            float4 q0 = g_boxes8[base + 0];
            float4 q1 = g_boxes8[base + 1];
            float* o = out + ((size_t)b * MAXDET + tid) * 6;
            o[0] = q0.x; o[1] = q0.y; o[2] = q0.z; o[3] = q0.w;
            o[4] = q1.x; o[5] = __uint_as_float((u32)(key >> 32));
        }
        return;
    }

    // ---------------- exact full-array fallback (normally unreachable) ----
    {
        float* scw = g_scores + (size_t)b * A;
        const float4* bx = g_boxes8 + (size_t)b * A * 2;
        for (int d = 0; d < MAXDET; d++) {
            u64 mk = 0;
            for (int i = tid; i < A; i += NMS_NT) {
                u64 k = ((u64)__float_as_uint(scw[i]) << 32) |
                        (u32)(0x7FFFFFFF - i);
                if (k > mk) mk = k;
            }
#pragma unroll
            for (int off = 16; off; off >>= 1) {
                u64 ok = __shfl_down_sync(0xffffffffu, mk, off);
                if (ok > mk) mk = ok;
            }
            if ((tid & 31) == 0) redk[tid >> 5] = mk;
            __syncthreads();
            if (tid < 32) {
                u64 k2 = (tid < NMS_NT / 32) ? redk[tid] : 0ull;
#pragma unroll
                for (int off = 16; off; off >>= 1) {
                    u64 ok = __shfl_down_sync(0xffffffffu, k2, off);
                    if (ok > k2) k2 = ok;
                }
                if (tid == 0) sBest = k2;
            }
            __syncthreads();
            u64 selKey = sBest;
            int   a = 0x7FFFFFFF - (int)(selKey & 0xFFFFFFFFull);
            float selScore = __uint_as_float((u32)(selKey >> 32));
            float4 q0 = bx[(size_t)a * 2 + 0];
            float4 q1 = bx[(size_t)a * 2 + 1];
            float X1 = q0.x - 0.5f * q0.z, Y1 = q0.y - 0.5f * q0.w;
            float X2 = q0.x + 0.5f * q0.z, Y2 = q0.y + 0.5f * q0.w;
            float AR = q0.z * q0.w;
            int   CL = (int)q1.x;
            if (tid == 0) {
                float* o = out + ((size_t)b * MAXDET + d) * 6;
                o[0] = q0.x; o[1] = q0.y; o[2] = q0.z;
                o[3] = q0.w; o[4] = q1.x; o[5] = selScore;
            }
            __syncthreads();
            for (int i = tid; i < A; i += NMS_NT) {
                if (i == a) { scw[i] = 0.0f; continue; }
                if (scw[i] == 0.0f) continue;
                float4 r0 = bx[(size_t)i * 2 + 0];
                float4 r1 = bx[(size_t)i * 2 + 1];
                if ((int)r1.x == CL) {
                    float iw = fminf(r0.x + 0.5f * r0.z, X2) - fmaxf(r0.x - 0.5f * r0.z, X1);
                    float ih = fminf(r0.y + 0.5f * r0.w, Y2) - fmaxf(r0.y - 0.5f * r0.w, Y1);
                    if (iw > 0.0f && ih > 0.0f) {
                        float inter = iw * ih;
                        float iou = inter / (r0.z * r0.w + AR - inter + 1e-8f);
                        if (iou > IOU_T) scw[i] = 0.0f;
                    }
                }
            }
            __syncthreads();
        }
    }
}

// ---------------- launch ----------------
extern "C" void kernel_launch(void* const* d_in, const int* in_sizes, int n_in,
                              void* d_out, int out_size) {
    const float *pred, *anch;
    int s0 = in_sizes[0], s1 = in_sizes[1];
    if (s0 >= s1) {
        pred = (const float*)d_in[0]; anch = (const float*)d_in[1];
    } else {
        pred = (const float*)d_in[1]; anch = (const float*)d_in[0];
        int t = s0; s0 = s1; s1 = t;
    }
    int A = s1 / 4;
    int B = out_size / (MAXDET * 6);
    int total = B * A;

    decode_kernel<<<(total * 4 + 255) / 256, 256>>>(pred, anch, B, A);
    thresh_kernel<<<B, 512>>>();

    static int smem_set = 0;
    if (!smem_set) {
        cudaFuncSetAttribute(nms_kernel,
                             cudaFuncAttributeMaxDynamicSharedMemorySize, NMS_SMEM);
        smem_set = 1;
    }
    nms_kernel<<<B, NMS_NT, NMS_SMEM>>>((float*)d_out, A);
}

// round 12
// speedup vs baseline: 1.0401x; 1.0401x over previous
#include <cuda_runtime.h>

#define DPRED    84
#define NCLS     80
#define MAXB     8
#define MAXA     76725
#define NBINS    4096
#define KMAX     512
#define NW       (KMAX / 32)
#define KTARGET  128
#define MAXDET   100
#define CONF_T   0.05f
#define IOU_T    0.5f
#define NMS_NT   256

typedef unsigned long long u64;
typedef unsigned int       u32;

// dynamic smem layout (bytes)
#define SM_SK    0
#define SM_MAT   (SM_SK  + KMAX * 8)     // also reused as hist scratch (16KB<32KB)
#define SM_X1    (SM_MAT + KMAX * NW * 4)
#define SM_Y1    (SM_X1  + KMAX * 4)
#define SM_X2    (SM_Y1  + KMAX * 4)
#define SM_Y2    (SM_X2  + KMAX * 4)
#define SM_AR    (SM_Y2  + KMAX * 4)
#define SM_CL    (SM_AR  + KMAX * 4)
#define SM_CAND  (SM_CL  + KMAX * 4)
#define SM_FLAG  (SM_CAND + KMAX * 4)
#define SM_DEAD  (SM_FLAG + NW * 4)
#define SM_ALIVE (SM_DEAD + NW * 4)
#define NMS_SMEM (SM_ALIVE + KMAX * 2)

// ---------------- device scratch (no allocation allowed) ----------------
__device__ float4 g_boxes8[MAXB * MAXA * 2];  // cx,cy,w,h | cls,conf,0,0
__device__ float  g_scores[MAXB * MAXA];      // conf if >= CONF_T else 0
__device__ int    g_hist[MAXB * NBINS];       // zero-init; re-zeroed in nms

// ---------------- decode: thread per anchor (measured best) --------------
__global__ void __launch_bounds__(256)
decode_kernel(const float* __restrict__ pred,
              const float* __restrict__ anchors,
              int B, int A) {
    int i = blockIdx.x * blockDim.x + threadIdx.x;
    if (i >= B * A) return;

    const float4* row = reinterpret_cast<const float4*>(pred + (size_t)i * DPRED);
    float4 v0 = __ldg(row + 0);

    float best = -3.4e38f;
    int   cls  = 0;
#pragma unroll
    for (int j = 1; j <= 20; j++) {
        float4 c = __ldg(row + j);
        int base = (j - 1) * 4;
        if (c.x > best) { best = c.x; cls = base + 0; }
        if (c.y > best) { best = c.y; cls = base + 1; }
        if (c.z > best) { best = c.z; cls = base + 2; }
        if (c.w > best) { best = c.w; cls = base + 3; }
    }

    int b = i / A;
    int a = i - b * A;

    float4 an = __ldg(reinterpret_cast<const float4*>(anchors) + a);
    float cx = v0.x * 0.1f * an.z + an.x;
    float cy = v0.y * 0.1f * an.w + an.y;
    float w  = expf(v0.z * 0.2f) * an.z;
    float h  = expf(v0.w * 0.2f) * an.w;
    float conf = 1.0f / (1.0f + expf(-best));

    g_boxes8[(size_t)i * 2 + 0] = make_float4(cx, cy, w, h);
    g_boxes8[(size_t)i * 2 + 1] = make_float4((float)cls, conf, 0.f, 0.f);

    float s = (conf >= CONF_T) ? conf : 0.0f;
    g_scores[i] = s;
    if (s > 0.0f) {
        int bin = (int)(s * (float)NBINS);
        if (bin > NBINS - 1) bin = NBINS - 1;
        if (bin < 1) bin = 1;
        atomicAdd(&g_hist[b * NBINS + bin], 1);
    }
}

// --- NMS: fused thresh + compact + sort + matrix + resolve (+fallback) ---
__global__ void __launch_bounds__(NMS_NT, 1)
nms_kernel(float* __restrict__ out, int A) {
    extern __shared__ char dynsm[];
    u64*   sk     = (u64*)  (dynsm + SM_SK);
    u32*   mat    = (u32*)  (dynsm + SM_MAT);
    float* sx1    = (float*)(dynsm + SM_X1);
    float* sy1    = (float*)(dynsm + SM_Y1);
    float* sx2    = (float*)(dynsm + SM_X2);
    float* sy2    = (float*)(dynsm + SM_Y2);
    float* sar    = (float*)(dynsm + SM_AR);
    float* scl    = (float*)(dynsm + SM_CL);
    int*   scand  = (int*)  (dynsm + SM_CAND);
    u32*   flagm  = (u32*)  (dynsm + SM_FLAG);
    u32*   sdead  = (u32*)  (dynsm + SM_DEAD);
    unsigned short* aliveL = (unsigned short*)(dynsm + SM_ALIVE);

    __shared__ int   csum[128];
    __shared__ float sTh;
    __shared__ int   sFallback, sCtr;
    __shared__ u64   sBest;
    __shared__ u64   redk[NMS_NT / 32];

    int b   = blockIdx.x;
    int tid = threadIdx.x;

    // ---- threshold from histogram (hist staged in mat scratch) ----
    int* hist = (int*)mat;              // 16KB scratch inside 32KB mat region
    for (int i = tid; i < NBINS; i += NMS_NT)
        hist[i] = g_hist[b * NBINS + i];
    __syncthreads();
    for (int i = tid; i < NBINS; i += NMS_NT)
        g_hist[b * NBINS + i] = 0;      // re-zero for next graph replay

    if (tid < 128) {
        int s = 0, base = tid * 32;
#pragma unroll
        for (int j = 0; j < 32; j++) s += hist[base + j];
        csum[tid] = s;
    }
    __syncthreads();

    if (tid == 0) {
        int cum = 0, binSel = NBINS, c = 128;
        while (c > 1 && cum < KTARGET && cum + csum[c - 1] <= KMAX) {
            c--; cum += csum[c]; binSel = c * 32;
        }
        if (cum < KTARGET && c >= 1) {
            for (int bin = c * 32 - 1; bin >= (c - 1) * 32 && bin >= 1; --bin) {
                int h = hist[bin];
                if (cum + h > KMAX) break;
                cum += h; binSel = bin;
                if (cum >= KTARGET) break;
            }
        }
        sTh  = (float)binSel / (float)NBINS;
        sCtr = 0;
    }
    __syncthreads();

    // ---- in-kernel compact: scores > thresh -> smem candidate list ----
    float th = sTh;
    const float* sc = g_scores + (size_t)b * A;
    for (int i = tid; i < A; i += NMS_NT) {
        if (sc[i] > th) {
            int p = atomicAdd(&sCtr, 1);
            if (p < KMAX) scand[p] = i;
        }
    }
    __syncthreads();

    int cnt = sCtr;
    bool overflow = (cnt > KMAX);
    if (cnt > KMAX) cnt = KMAX;

    // keys (conf hi, 0x7FFFFFFF - anchor lo); pad with 0
    for (int i = tid; i < KMAX; i += NMS_NT) {
        u64 k = 0;
        if (i < cnt) {
            int a = scand[i];
            float4 p1 = g_boxes8[((size_t)b * A + a) * 2 + 1];
            k = ((u64)__float_as_uint(p1.y) << 32) | (u32)(0x7FFFFFFF - a);
        }
        sk[i] = k;
    }
    // zero matrix / masks (overwrites hist scratch)
    for (int t = tid; t < KMAX * NW; t += NMS_NT) mat[t] = 0;
    if (tid < NW) { flagm[tid] = 0; sdead[tid] = 0; }
    if (tid == 0) sFallback = overflow ? 1 : 0;
    __syncthreads();

    // ---- bitonic sort, descending ----
    for (int k2 = 2; k2 <= KMAX; k2 <<= 1) {
        for (int j2 = k2 >> 1; j2 > 0; j2 >>= 1) {
            for (int i = tid; i < KMAX; i += NMS_NT) {
                int p = i ^ j2;
                if (p > i) {
                    u64 a = sk[i], c = sk[p];
                    bool descBlk = ((i & k2) == 0);
                    if (descBlk ? (a < c) : (a > c)) { sk[i] = c; sk[p] = a; }
                }
            }
            __syncthreads();
        }
    }

    // ---- gather box data for sorted slots ----
    for (int s = tid; s < KMAX; s += NMS_NT) {
        u64 key = sk[s];
        if (key != 0) {
            int a = 0x7FFFFFFF - (int)(key & 0xFFFFFFFFull);
            size_t base = ((size_t)b * A + a) * 2;
            float4 p0 = g_boxes8[base + 0];
            float4 p1 = g_boxes8[base + 1];
            float hw = 0.5f * p0.z, hh = 0.5f * p0.w;
            sx1[s] = p0.x - hw; sy1[s] = p0.y - hh;
            sx2[s] = p0.x + hw; sy2[s] = p0.y + hh;
            sar[s] = p0.z * p0.w;
            scl[s] = p1.x;
        } else {
            scl[s] = -1.0f;
        }
    }
    __syncthreads();

    // ---- suppression matrix: row i suppresses j>i (mirror-paired rows) ----
#pragma unroll
    for (int half = 0; half < 2; half++) {
        int i = half ? (KMAX - 1 - tid) : tid;
        if (i >= cnt || (half && i == tid)) continue;
        float ci = scl[i];
        float X1 = sx1[i], Y1 = sy1[i], X2 = sx2[i], Y2 = sy2[i];
        float AR = sar[i];
        u32 bits = 0; u32 rowany = 0;
        int wcur = (i + 1) >> 5;
        for (int j = i + 1; j < cnt; j++) {
            int w = j >> 5;
            if (w != wcur) {
                if (bits) { mat[i * NW + wcur] = bits; rowany = 1; }
                bits = 0; wcur = w;
            }
            if (scl[j] == ci) {
                float iw = fminf(sx2[j], X2) - fmaxf(sx1[j], X1);
                float ih = fminf(sy2[j], Y2) - fmaxf(sy1[j], Y1);
                if (iw > 0.0f && ih > 0.0f) {
                    float inter = iw * ih;
                    float iou = inter / (sar[j] + AR - inter + 1e-8f);
                    if (iou > IOU_T) bits |= 1u << (j & 31);
                }
            }
        }
        if (bits) { mat[i * NW + wcur] = bits; rowany = 1; }
        if (rowany) atomicOr(&flagm[i >> 5], 1u << (i & 31));
    }
    __syncthreads();

    // ---- resolve: greedy over sorted order via bitmasks ----
    if (tid == 0 && !sFallback) {
        int aliveCnt = 0;
#pragma unroll
        for (int w = 0; w < NW; w++) {
            int lo = w * 32;
            int nvalid = cnt - lo;
            if (nvalid <= 0) break;
            u32 validm = (nvalid >= 32) ? 0xFFFFFFFFu : ((1u << nvalid) - 1u);
            u32 candm = validm & ~sdead[w];
            u32 fl = flagm[w];
            while (candm) {
                int bb = __ffs(candm) - 1;
                candm &= candm - 1;
                aliveL[aliveCnt++] = (unsigned short)(lo + bb);
                if (fl & (1u << bb)) {
                    int i = lo + bb;
#pragma unroll
                    for (int ww = 0; ww < NW; ww++)
                        sdead[ww] |= mat[i * NW + ww];
                    candm &= ~sdead[w];
                }
            }
        }
        if (aliveCnt < MAXDET) sFallback = 1;   // pool exhausted -> exact
    }
    __syncthreads();

    // ---- output: first MAXDET alive in sorted order ----
    if (!sFallback) {
        if (tid < MAXDET) {
            int s = aliveL[tid];
            u64 key = sk[s];
            int a = 0x7FFFFFFF - (int)(key & 0xFFFFFFFFull);
            size_t base = ((size_t)b * A + a) * 2;
            float4 p0 = g_boxes8[base + 0];
            float4 p1 = g_boxes8[base + 1];
            float* o = out + ((size_t)b * MAXDET + tid) * 6;
            o[0] = p0.x; o[1] = p0.y; o[2] = p0.z; o[3] = p0.w;
            o[4] = p1.x; o[5] = __uint_as_float((u32)(key >> 32));
        }
        return;
    }

    // ---------------- exact full-array fallback (normally unreachable) ----
    {
        float* scw = g_scores + (size_t)b * A;
        const float4* bx = g_boxes8 + (size_t)b * A * 2;
        for (int d = 0; d < MAXDET; d++) {
            u64 mk = 0;
            for (int i = tid; i < A; i += NMS_NT) {
                u64 k = ((u64)__float_as_uint(scw[i]) << 32) |
                        (u32)(0x7FFFFFFF - i);
                if (k > mk) mk = k;
            }
#pragma unroll
            for (int off = 16; off; off >>= 1) {
                u64 ok = __shfl_down_sync(0xffffffffu, mk, off);
                if (ok > mk) mk = ok;
            }
            if ((tid & 31) == 0) redk[tid >> 5] = mk;
            __syncthreads();
            if (tid < 32) {
                u64 k2 = (tid < NMS_NT / 32) ? redk[tid] : 0ull;
#pragma unroll
                for (int off = 16; off; off >>= 1) {
                    u64 ok = __shfl_down_sync(0xffffffffu, k2, off);
                    if (ok > k2) k2 = ok;
                }
                if (tid == 0) sBest = k2;
            }
            __syncthreads();
            u64 selKey = sBest;
            int   a = 0x7FFFFFFF - (int)(selKey & 0xFFFFFFFFull);
            float selScore = __uint_as_float((u32)(selKey >> 32));
            float4 p0 = bx[(size_t)a * 2 + 0];
            float4 p1 = bx[(size_t)a * 2 + 1];
            float X1 = p0.x - 0.5f * p0.z, Y1 = p0.y - 0.5f * p0.w;
            float X2 = p0.x + 0.5f * p0.z, Y2 = p0.y + 0.5f * p0.w;
            float AR = p0.z * p0.w;
            int   CL = (int)p1.x;
            if (tid == 0) {
                float* o = out + ((size_t)b * MAXDET + d) * 6;
                o[0] = p0.x; o[1] = p0.y; o[2] = p0.z;
                o[3] = p0.w; o[4] = p1.x; o[5] = selScore;
            }
            __syncthreads();
            for (int i = tid; i < A; i += NMS_NT) {
                if (i == a) { scw[i] = 0.0f; continue; }
                if (scw[i] == 0.0f) continue;
                float4 q0 = bx[(size_t)i * 2 + 0];
                float4 q1 = bx[(size_t)i * 2 + 1];
                if ((int)q1.x == CL) {
                    float iw = fminf(q0.x + 0.5f * q0.z, X2) - fmaxf(q0.x - 0.5f * q0.z, X1);
                    float ih = fminf(q0.y + 0.5f * q0.w, Y2) - fmaxf(q0.y - 0.5f * q0.w, Y1);
                    if (iw > 0.0f && ih > 0.0f) {
                        float inter = iw * ih;
                        float iou = inter / (q0.z * q0.w + AR - inter + 1e-8f);
                        if (iou > IOU_T) scw[i] = 0.0f;
                    }
                }
            }
            __syncthreads();
        }
    }
}

// ---------------- launch ----------------
extern "C" void kernel_launch(void* const* d_in, const int* in_sizes, int n_in,
                              void* d_out, int out_size) {
    const float *pred, *anch;
    int s0 = in_sizes[0], s1 = in_sizes[1];
    if (s0 >= s1) {
        pred = (const float*)d_in[0]; anch = (const float*)d_in[1];
    } else {
        pred = (const float*)d_in[1]; anch = (const float*)d_in[0];
        int t = s0; s0 = s1; s1 = t;
    }
    int A = s1 / 4;
    int B = out_size / (MAXDET * 6);
    int total = B * A;

    decode_kernel<<<(total + 255) / 256, 256>>>(pred, anch, B, A);

    static int smem_set = 0;
    if (!smem_set) {
        cudaFuncSetAttribute(nms_kernel,
                             cudaFuncAttributeMaxDynamicSharedMemorySize, NMS_SMEM);
        smem_set = 1;
    }
    nms_kernel<<<B, NMS_NT, NMS_SMEM>>>((float*)d_out, A);
}

// round 13
// speedup vs baseline: 1.4060x; 1.3518x over previous
#include <cuda_runtime.h>

#define DPRED    84
#define NCLS     80
#define MAXB     8
#define MAXA     76725
#define NBINS    4096
#define KMAX     512
#define NW       (KMAX / 32)
#define KTARGET  128
#define MAXDET   100
#define CONF_T   0.05f
#define IOU_T    0.5f
#define CP_NT    256
#define NMS_NT   256

typedef unsigned long long u64;
typedef unsigned int       u32;

// nms dynamic smem layout (bytes)
#define SM_SK    0
#define SM_MAT   (SM_SK  + KMAX * 8)
#define SM_X1    (SM_MAT + KMAX * NW * 4)
#define SM_Y1    (SM_X1  + KMAX * 4)
#define SM_X2    (SM_Y1  + KMAX * 4)
#define SM_Y2    (SM_X2  + KMAX * 4)
#define SM_AR    (SM_Y2  + KMAX * 4)
#define SM_CL    (SM_AR  + KMAX * 4)
#define SM_PB    (SM_CL  + KMAX * 4)
#define SM_FLAG  (SM_PB  + KMAX * 16)
#define SM_DEAD  (SM_FLAG + NW * 4)
#define SM_ALIVE (SM_DEAD + NW * 4)
#define NMS_SMEM (SM_ALIVE + KMAX * 2)

// ---------------- device scratch (no allocation allowed) ----------------
__device__ float  g_scores[MAXB * MAXA];      // conf if >= CONF_T else 0
__device__ int    g_hist[MAXB * NBINS];       // zero-init; re-zeroed in nms
__device__ u64    g_cand[MAXB * KMAX];        // sort keys
__device__ int    g_cnt[MAXB];                // zero-init; re-zeroed in nms
__device__ float4 g_boxes8[MAXB * MAXA * 2];  // fallback-only scratch

// ---------------- score: thread per anchor, max-only ----------------
__global__ void __launch_bounds__(256)
score_kernel(const float* __restrict__ pred, int B, int A) {
    int i = blockIdx.x * blockDim.x + threadIdx.x;
    if (i >= B * A) return;

    const float4* row = reinterpret_cast<const float4*>(pred + (size_t)i * DPRED);
    float m0 = -3.4e38f, m1 = -3.4e38f, m2 = -3.4e38f, m3 = -3.4e38f;
#pragma unroll
    for (int j = 1; j <= 20; j++) {
        float4 c = __ldg(row + j);
        m0 = fmaxf(m0, c.x); m1 = fmaxf(m1, c.y);
        m2 = fmaxf(m2, c.z); m3 = fmaxf(m3, c.w);
    }
    float best = fmaxf(fmaxf(m0, m1), fmaxf(m2, m3));
    float conf = 1.0f / (1.0f + expf(-best));
    float s = (conf >= CONF_T) ? conf : 0.0f;
    g_scores[i] = s;
    if (s > 0.0f) {
        int b = i / A;
        int bin = (int)(s * (float)NBINS);
        if (bin > NBINS - 1) bin = NBINS - 1;
        if (bin < 1) bin = 1;
        atomicAdd(&g_hist[b * NBINS + bin], 1);
    }
}

// ------- compact: per-block threshold walk + key emission ---------------
__global__ void __launch_bounds__(CP_NT)
compact_kernel(int A) {
    __shared__ int   hist[NBINS];
    __shared__ int   csum[128];
    __shared__ float sTh;
    int b   = blockIdx.y;
    int tid = threadIdx.x;

    for (int i = tid; i < NBINS; i += CP_NT)
        hist[i] = g_hist[b * NBINS + i];
    __syncthreads();

    if (tid < 128) {
        int s = 0, base = tid * 32;
#pragma unroll
        for (int j = 0; j < 32; j++) s += hist[base + j];
        csum[tid] = s;
    }
    __syncthreads();

    if (tid == 0) {
        int cum = 0, binSel = NBINS, c = 128;
        while (c > 1 && cum < KTARGET && cum + csum[c - 1] <= KMAX) {
            c--; cum += csum[c]; binSel = c * 32;
        }
        if (cum < KTARGET && c >= 1) {
            for (int bin = c * 32 - 1; bin >= (c - 1) * 32 && bin >= 1; --bin) {
                int h = hist[bin];
                if (cum + h > KMAX) break;
                cum += h; binSel = bin;
                if (cum >= KTARGET) break;
            }
        }
        sTh = (float)binSel / (float)NBINS;
    }
    __syncthreads();

    float th = sTh;
    const float* sc = g_scores + (size_t)b * A;
    for (int i = blockIdx.x * CP_NT + tid; i < A; i += gridDim.x * CP_NT) {
        float s = sc[i];
        if (s > th) {
            int p = atomicAdd(&g_cnt[b], 1);
            if (p < KMAX)
                g_cand[b * KMAX + p] =
                    ((u64)__float_as_uint(s) << 32) | (u32)(0x7FFFFFFF - i);
        }
    }
}

// ---- NMS: sort keys + re-decode candidates + matrix + resolve ----------
__global__ void __launch_bounds__(NMS_NT, 1)
nms_kernel(float* __restrict__ out,
           const float* __restrict__ pred,
           const float* __restrict__ anchors, int A) {
    extern __shared__ char dynsm[];
    u64*    sk    = (u64*)   (dynsm + SM_SK);
    u32*    mat   = (u32*)   (dynsm + SM_MAT);
    float*  sx1   = (float*) (dynsm + SM_X1);
    float*  sy1   = (float*) (dynsm + SM_Y1);
    float*  sx2   = (float*) (dynsm + SM_X2);
    float*  sy2   = (float*) (dynsm + SM_Y2);
    float*  sar   = (float*) (dynsm + SM_AR);
    float*  scl   = (float*) (dynsm + SM_CL);
    float4* pbox  = (float4*)(dynsm + SM_PB);
    u32*    flagm = (u32*)   (dynsm + SM_FLAG);
    u32*    sdead = (u32*)   (dynsm + SM_DEAD);
    unsigned short* aliveL = (unsigned short*)(dynsm + SM_ALIVE);

    __shared__ int sFallback, sCnt;
    __shared__ u64 sBest;
    __shared__ u64 redk[NMS_NT / 32];

    int b   = blockIdx.x;
    int tid = threadIdx.x;

    // reset pipeline state for next graph replay; capture cnt
    for (int i = tid; i < NBINS; i += NMS_NT) g_hist[b * NBINS + i] = 0;
    if (tid == 0) { sCnt = g_cnt[b]; g_cnt[b] = 0; }
    if (tid < NW) { flagm[tid] = 0; sdead[tid] = 0; }
    __syncthreads();

    int cnt = sCnt;
    bool overflow = (cnt > KMAX);
    if (cnt > KMAX) cnt = KMAX;
    if (tid == 0) sFallback = overflow ? 1 : 0;

    for (int i = tid; i < KMAX; i += NMS_NT)
        sk[i] = (i < cnt) ? g_cand[b * KMAX + i] : 0ull;
    for (int t = tid; t < KMAX * NW; t += NMS_NT) mat[t] = 0;
    __syncthreads();

    // ---- bitonic sort, descending ----
    for (int k2 = 2; k2 <= KMAX; k2 <<= 1) {
        for (int j2 = k2 >> 1; j2 > 0; j2 >>= 1) {
            for (int i = tid; i < KMAX; i += NMS_NT) {
                int p = i ^ j2;
                if (p > i) {
                    u64 a = sk[i], c = sk[p];
                    bool descBlk = ((i & k2) == 0);
                    if (descBlk ? (a < c) : (a > c)) { sk[i] = c; sk[p] = a; }
                }
            }
            __syncthreads();
        }
    }

    // ---- re-decode candidates (box + cls) for sorted slots ----
    for (int s = tid; s < KMAX; s += NMS_NT) {
        if (s < cnt) {
            int a = 0x7FFFFFFF - (int)(sk[s] & 0xFFFFFFFFull);
            const float4* row =
                reinterpret_cast<const float4*>(pred + ((size_t)b * A + a) * DPRED);
            float4 v0 = __ldg(row + 0);
            float best = -3.4e38f;
            int   cls  = 0;
#pragma unroll
            for (int j = 1; j <= 20; j++) {
                float4 c = __ldg(row + j);
                int base = (j - 1) * 4;
                if (c.x > best) { best = c.x; cls = base + 0; }
                if (c.y > best) { best = c.y; cls = base + 1; }
                if (c.z > best) { best = c.z; cls = base + 2; }
                if (c.w > best) { best = c.w; cls = base + 3; }
            }
            float4 an = __ldg(reinterpret_cast<const float4*>(anchors) + a);
            float cx = v0.x * 0.1f * an.z + an.x;
            float cy = v0.y * 0.1f * an.w + an.y;
            float w  = expf(v0.z * 0.2f) * an.z;
            float h  = expf(v0.w * 0.2f) * an.w;
            float hw = 0.5f * w, hh = 0.5f * h;
            sx1[s] = cx - hw; sy1[s] = cy - hh;
            sx2[s] = cx + hw; sy2[s] = cy + hh;
            sar[s] = w * h;
            scl[s] = (float)cls;
            pbox[s] = make_float4(cx, cy, w, h);
        } else {
            scl[s] = -1.0f;
        }
    }
    __syncthreads();

    // ---- suppression matrix: row i suppresses j>i (mirror-paired rows) ----
#pragma unroll
    for (int half = 0; half < 2; half++) {
        int i = half ? (KMAX - 1 - tid) : tid;
        if (i >= cnt || (half && i == tid)) continue;
        float ci = scl[i];
        float X1 = sx1[i], Y1 = sy1[i], X2 = sx2[i], Y2 = sy2[i];
        float AR = sar[i];
        u32 bits = 0; u32 rowany = 0;
        int wcur = (i + 1) >> 5;
        for (int j = i + 1; j < cnt; j++) {
            int w = j >> 5;
            if (w != wcur) {
                if (bits) { mat[i * NW + wcur] = bits; rowany = 1; }
                bits = 0; wcur = w;
            }
            if (scl[j] == ci) {
                float iw = fminf(sx2[j], X2) - fmaxf(sx1[j], X1);
                float ih = fminf(sy2[j], Y2) - fmaxf(sy1[j], Y1);
                if (iw > 0.0f && ih > 0.0f) {
                    float inter = iw * ih;
                    float iou = inter / (sar[j] + AR - inter + 1e-8f);
                    if (iou > IOU_T) bits |= 1u << (j & 31);
                }
            }
        }
        if (bits) { mat[i * NW + wcur] = bits; rowany = 1; }
        if (rowany) atomicOr(&flagm[i >> 5], 1u << (i & 31));
    }
    __syncthreads();

    // ---- resolve: greedy over sorted order via bitmasks ----
    if (tid == 0 && !sFallback) {
        int aliveCnt = 0;
#pragma unroll
        for (int w = 0; w < NW; w++) {
            int lo = w * 32;
            int nvalid = cnt - lo;
            if (nvalid <= 0) break;
            u32 validm = (nvalid >= 32) ? 0xFFFFFFFFu : ((1u << nvalid) - 1u);
            u32 candm = validm & ~sdead[w];
            u32 fl = flagm[w];
            while (candm) {
                int bb = __ffs(candm) - 1;
                candm &= candm - 1;
                aliveL[aliveCnt++] = (unsigned short)(lo + bb);
                if (fl & (1u << bb)) {
                    int i = lo + bb;
#pragma unroll
                    for (int ww = 0; ww < NW; ww++)
                        sdead[ww] |= mat[i * NW + ww];
                    candm &= ~sdead[w];
                }
            }
        }
        if (aliveCnt < MAXDET) sFallback = 1;   // pool exhausted -> exact
    }
    __syncthreads();

    // ---- output: first MAXDET alive in sorted order ----
    if (!sFallback) {
        if (tid < MAXDET) {
            int s = aliveL[tid];
            float4 p = pbox[s];
            float* o = out + ((size_t)b * MAXDET + tid) * 6;
            o[0] = p.x; o[1] = p.y; o[2] = p.z; o[3] = p.w;
            o[4] = scl[s];
            o[5] = __uint_as_float((u32)(sk[s] >> 32));
        }
        return;
    }

    // ---------- exact full-array fallback (normally unreachable) ----------
    {
        // materialize boxes for this batch
        for (int i = tid; i < A; i += NMS_NT) {
            const float4* row =
                reinterpret_cast<const float4*>(pred + ((size_t)b * A + i) * DPRED);
            float4 v0 = __ldg(row + 0);
            float best = -3.4e38f;
            int   cls  = 0;
#pragma unroll
            for (int j = 1; j <= 20; j++) {
                float4 c = __ldg(row + j);
                int base = (j - 1) * 4;
                if (c.x > best) { best = c.x; cls = base + 0; }
                if (c.y > best) { best = c.y; cls = base + 1; }
                if (c.z > best) { best = c.z; cls = base + 2; }
                if (c.w > best) { best = c.w; cls = base + 3; }
            }
            float4 an = __ldg(reinterpret_cast<const float4*>(anchors) + i);
            float cx = v0.x * 0.1f * an.z + an.x;
            float cy = v0.y * 0.1f * an.w + an.y;
            float w  = expf(v0.z * 0.2f) * an.z;
            float h  = expf(v0.w * 0.2f) * an.w;
            g_boxes8[((size_t)b * A + i) * 2 + 0] = make_float4(cx, cy, w, h);
            g_boxes8[((size_t)b * A + i) * 2 + 1] = make_float4((float)cls, 0.f, 0.f, 0.f);
        }
        __syncthreads();

        float* scw = g_scores + (size_t)b * A;
        const float4* bx = g_boxes8 + (size_t)b * A * 2;
        for (int d = 0; d < MAXDET; d++) {
            u64 mk = 0;
            for (int i = tid; i < A; i += NMS_NT) {
                u64 k = ((u64)__float_as_uint(scw[i]) << 32) |
                        (u32)(0x7FFFFFFF - i);
                if (k > mk) mk = k;
            }
#pragma unroll
            for (int off = 16; off; off >>= 1) {
                u64 ok = __shfl_down_sync(0xffffffffu, mk, off);
                if (ok > mk) mk = ok;
            }
            if ((tid & 31) == 0) redk[tid >> 5] = mk;
            __syncthreads();
            if (tid < 32) {
                u64 k2 = (tid < NMS_NT / 32) ? redk[tid] : 0ull;
#pragma unroll
                for (int off = 16; off; off >>= 1) {
                    u64 ok = __shfl_down_sync(0xffffffffu, k2, off);
                    if (ok > k2) k2 = ok;
                }
                if (tid == 0) sBest = k2;
            }
            __syncthreads();
            u64 selKey = sBest;
            int   a = 0x7FFFFFFF - (int)(selKey & 0xFFFFFFFFull);
            float selScore = __uint_as_float((u32)(selKey >> 32));
            float4 p0 = bx[(size_t)a * 2 + 0];
            float4 p1 = bx[(size_t)a * 2 + 1];
            float X1 = p0.x - 0.5f * p0.z, Y1 = p0.y - 0.5f * p0.w;
            float X2 = p0.x + 0.5f * p0.z, Y2 = p0.y + 0.5f * p0.w;
            float AR = p0.z * p0.w;
            int   CL = (int)p1.x;
            if (tid == 0) {
                float* o = out + ((size_t)b * MAXDET + d) * 6;
                o[0] = p0.x; o[1] = p0.y; o[2] = p0.z;
                o[3] = p0.w; o[4] = p1.x; o[5] = selScore;
            }
            __syncthreads();
            for (int i = tid; i < A; i += NMS_NT) {
                if (i == a) { scw[i] = 0.0f; continue; }
                if (scw[i] == 0.0f) continue;
                float4 q0 = bx[(size_t)i * 2 + 0];
                float4 q1 = bx[(size_t)i * 2 + 1];
                if ((int)q1.x == CL) {
                    float iw = fminf(q0.x + 0.5f * q0.z, X2) - fmaxf(q0.x - 0.5f * q0.z, X1);
                    float ih = fminf(q0.y + 0.5f * q0.w, Y2) - fmaxf(q0.y - 0.5f * q0.w, Y1);
                    if (iw > 0.0f && ih > 0.0f) {
                        float inter = iw * ih;
                        float iou = inter / (q0.z * q0.w + AR - inter + 1e-8f);
                        if (iou > IOU_T) scw[i] = 0.0f;
                    }
                }
            }
            __syncthreads();
        }
    }
}

// ---------------- launch ----------------
extern "C" void kernel_launch(void* const* d_in, const int* in_sizes, int n_in,
                              void* d_out, int out_size) {
    const float *pred, *anch;
    int s0 = in_sizes[0], s1 = in_sizes[1];
    if (s0 >= s1) {
        pred = (const float*)d_in[0]; anch = (const float*)d_in[1];
    } else {
        pred = (const float*)d_in[1]; anch = (const float*)d_in[0];
        int t = s0; s0 = s1; s1 = t;
    }
    int A = s1 / 4;
    int B = out_size / (MAXDET * 6);
    int total = B * A;

    score_kernel<<<(total + 255) / 256, 256>>>(pred, B, A);
    compact_kernel<<<dim3(64, B), CP_NT>>>(A);

    static int smem_set = 0;
    if (!smem_set) {
        cudaFuncSetAttribute(nms_kernel,
                             cudaFuncAttributeMaxDynamicSharedMemorySize, NMS_SMEM);
        smem_set = 1;
    }
    nms_kernel<<<B, NMS_NT, NMS_SMEM>>>((float*)d_out, pred, anch, A);
}